// round 16
// baseline (speedup 1.0000x reference)
#include <cuda_runtime.h>
#include <cuda_fp16.h>
#include <stdint.h>
#include <math.h>

#define S_TOT 32768
#define HD 32

// ---------------- scratch ----------------
__device__ __half g_qkv [S_TOT * 384];
__device__ __half g_sam [S_TOT * 128];
__device__ __half g_y1  [S_TOT * 128];
__device__ __half g_hid [S_TOT * 512];
__device__ float  g_t2  [S_TOT * 128];
__device__ __half g_qw  [384 * 128];
__device__ __half g_pw  [128 * 128];
__device__ __half g_w1f [512 * 128];
__device__ __half g_w2t [128 * 512];
__device__ float  g_b1f [512];
__device__ float  g_part[2 * S_TOT];
__device__ float  g_stats[512];         // m1,r1,m2,r2

// ---------------- helpers ----------------
__device__ __forceinline__ uint32_t smem_u32(const void* p) {
    uint32_t a;
    asm("{ .reg .u64 t; cvta.to.shared.u64 t, %1; cvt.u32.u64 %0, t; }"
        : "=r"(a) : "l"(p));
    return a;
}
__device__ __forceinline__ void cp16(uint32_t s, const void* g) {
    asm volatile("cp.async.cg.shared.global [%0], [%1], 16;" :: "r"(s), "l"(g));
}
__device__ __forceinline__ void cp16ca(uint32_t s, const void* g) {
    asm volatile("cp.async.ca.shared.global [%0], [%1], 16;" :: "r"(s), "l"(g));
}
__device__ __forceinline__ void cp_commit() {
    asm volatile("cp.async.commit_group;" ::: "memory");
}
template<int N>
__device__ __forceinline__ void cp_wait() {
    asm volatile("cp.async.wait_group %0;" :: "n"(N) : "memory");
}
__device__ __forceinline__ void ldsm4(uint32_t* r, uint32_t addr) {
    asm volatile("ldmatrix.sync.aligned.m8n8.x4.shared.b16 {%0,%1,%2,%3}, [%4];"
        : "=r"(r[0]), "=r"(r[1]), "=r"(r[2]), "=r"(r[3]) : "r"(addr));
}
__device__ __forceinline__ __half2 u2h(uint32_t u) {
    return *reinterpret_cast<__half2*>(&u);
}

// fp16 GEMM tiling: K-chunk 32 halfs, row stride 40 halfs
#define KSTRH 40
#define TILE_H (128 * KSTRH)

#define MMA_F16(acc, a, b) \
    asm volatile( \
        "mma.sync.aligned.m16n8k16.row.col.f32.f16.f16.f32 " \
        "{%0,%1,%2,%3}, {%4,%5,%6,%7}, {%8,%9}, {%0,%1,%2,%3};" \
        : "+f"((acc)[0]), "+f"((acc)[1]), "+f"((acc)[2]), "+f"((acc)[3]) \
        : "r"((a)[0]), "r"((a)[1]), "r"((a)[2]), "r"((a)[3]), \
          "r"((b)[0]), "r"((b)[1]))

// per-lane ldmatrix base offset given warp row base (bytes)
__device__ __forceinline__ uint32_t frag_off_row(int rowbase, int lane) {
    return (uint32_t)((rowbase + (lane & 15)) * (KSTRH * 2)
                      + ((lane >> 4) & 1) * 16);
}

// warp tile 64(M) x 32(N), one K32 chunk
__device__ __forceinline__ void gemm_chunk_h2(
    uint32_t aBase, uint32_t bBase, float acc[4][4][4])
{
#pragma unroll
    for (int ks = 0; ks < 2; ks++) {
        uint32_t a[4][4], b[4][2];
#pragma unroll
        for (int mi = 0; mi < 4; mi++)
            ldsm4(a[mi], aBase + (uint32_t)(mi * 16 * KSTRH * 2 + ks * 32));
#pragma unroll
        for (int n2 = 0; n2 < 2; n2++) {
            uint32_t r[4];
            ldsm4(r, bBase + (uint32_t)(n2 * 16 * KSTRH * 2 + ks * 32));
            b[2 * n2][0] = r[0]; b[2 * n2][1] = r[2];
            b[2 * n2 + 1][0] = r[1]; b[2 * n2 + 1][1] = r[3];
        }
#pragma unroll
        for (int mi = 0; mi < 4; mi++)
#pragma unroll
            for (int ni = 0; ni < 4; ni++)
                MMA_F16(acc[mi][ni], a[mi], b[ni]);
    }
}

// ============================================================
// A-resident multi-N fp16 GEMM (QKV, fc1): 256 thr, 8 warps (2Mx4N).
// TRANSX: A read from fp32 x [C, S_TOT], transposed+converted on load.
// smem: 4 A tiles + 2 B tiles = 61440 B.
// ============================================================
template<bool RELU, int NC, bool TRANSX>
__global__ void __launch_bounds__(256)
gemm_anc_h(const __half* __restrict__ A, const float* __restrict__ Ax,
           const __half* __restrict__ B,
           __half* __restrict__ Y, const float* __restrict__ bias, int Nout)
{
    extern __shared__ __half hsm[];

    const int tid = threadIdx.x;
    const int wid = tid >> 5;
    const int lane = tid & 31;
    const int wm = wid & 1;          // M warp (2)
    const int wn = wid >> 1;         // N warp (4)
    const int rq = lane >> 2;
    const int cq = lane & 3;
    const int s0 = blockIdx.x * 128;

    const uint32_t aOff = frag_off_row(wm * 64, lane);
    const uint32_t bOff = frag_off_row(wn * 32, lane);

    if (TRANSX) {
        // warp wid covers channels wid*16 + i; lanes cover S (coalesced)
#pragma unroll 4
        for (int i = 0; i < 16; i++) {
            const int c = wid * 16 + i;
            float4 v = *(const float4*)&Ax[(size_t)c * S_TOT + s0 + lane * 4];
            const int kc = c >> 5, cc = c & 31;
            __half* base = hsm + kc * TILE_H + cc;
            base[(lane * 4 + 0) * KSTRH] = __float2half(v.x);
            base[(lane * 4 + 1) * KSTRH] = __float2half(v.y);
            base[(lane * 4 + 2) * KSTRH] = __float2half(v.z);
            base[(lane * 4 + 3) * KSTRH] = __float2half(v.w);
        }
    } else {
#pragma unroll
        for (int kc = 0; kc < 4; kc++) {
            uint32_t aBase = smem_u32(hsm + kc * TILE_H);
#pragma unroll
            for (int j = 0; j < 2; j++) {
                int idx = tid + j * 256;
                int row = idx >> 2, seg = idx & 3;
                cp16(aBase + (uint32_t)(row * KSTRH * 2 + seg * 16),
                     &A[(size_t)(s0 + row) * 128 + kc * 32 + seg * 8]);
            }
        }
        cp_commit();
    }

    auto load_B = [&](int idx, int buf) {      // idx = nc*4 + kc
        const int nc = idx >> 2, kc = idx & 3;
        uint32_t bBase = smem_u32(hsm + (4 + buf) * TILE_H);
#pragma unroll
        for (int j = 0; j < 2; j++) {
            int l = tid + j * 256;
            int row = l >> 2, seg = l & 3;
            cp16(bBase + (uint32_t)(row * KSTRH * 2 + seg * 16),
                 &B[(size_t)(nc * 128 + row) * 128 + kc * 32 + seg * 8]);
        }
        cp_commit();
    };

    load_B(0, 0);

    for (int nc = 0; nc < NC; nc++) {
        float acc[4][4][4];
#pragma unroll
        for (int mi = 0; mi < 4; mi++)
#pragma unroll
            for (int ni = 0; ni < 4; ni++)
#pragma unroll
                for (int r = 0; r < 4; r++) acc[mi][ni][r] = 0.f;

        for (int kc = 0; kc < 4; kc++) {
            const int idx = nc * 4 + kc;
            if (idx + 1 < NC * 4) { load_B(idx + 1, (idx + 1) & 1); cp_wait<1>(); }
            else                  { cp_wait<0>(); }
            __syncthreads();
            gemm_chunk_h2(smem_u32(hsm + kc * TILE_H) + aOff,
                          smem_u32(hsm + (4 + (idx & 1)) * TILE_H) + bOff, acc);
            __syncthreads();
        }

        const int n0 = nc * 128;
#pragma unroll
        for (int ni = 0; ni < 4; ni++) {
            const int col = n0 + wn * 32 + ni * 8 + cq * 2;
            const float b0 = bias[col], b1 = bias[col + 1];
#pragma unroll
            for (int mi = 0; mi < 4; mi++) {
                const int row0 = s0 + wm * 64 + mi * 16 + rq;
#pragma unroll
                for (int half = 0; half < 2; half++) {
                    const int row = row0 + half * 8;
                    float v0 = acc[mi][ni][half * 2 + 0] + b0;
                    float v1 = acc[mi][ni][half * 2 + 1] + b1;
                    if (RELU) { v0 = fmaxf(v0, 0.f); v1 = fmaxf(v1, 0.f); }
                    *(__half2*)&Y[(size_t)row * Nout + col] =
                        __floats2half2_rn(v0, v1);
                }
            }
        }
    }
}

// ============================================================
// Streaming fp16 GEMM (proj, fc2): 256 thr, 8 warps, 3-stage, fused stats.
// ============================================================
template<bool RESID, bool OUTF32, bool STATS>
__global__ void __launch_bounds__(256)
gemm_h(const __half* __restrict__ A, const __half* __restrict__ B,
       void* __restrict__ Yv, const float* __restrict__ bias,
       int Kd, int Nout, const __half* __restrict__ resid,
       const float* __restrict__ mr, const float* __restrict__ rr,
       float* __restrict__ part)
{
    extern __shared__ __half hsm[];
    __shared__ float sstat[256];

    const int tid = threadIdx.x;
    const int wid = tid >> 5;
    const int lane = tid & 31;
    const int wm = wid & 1;
    const int wn = wid >> 1;
    const int rq = lane >> 2;
    const int cq = lane & 3;
    const int s0 = blockIdx.x * 128;
    const int n0 = blockIdx.y * 128;

    if (STATS) { sstat[tid] = 0.f; }
    // sstat covers 256 entries (sum:0-127, sq:128-255); tid covers all

    const int nch = Kd >> 5;
    const uint32_t aOff = frag_off_row(wm * 64, lane);
    const uint32_t bOff = frag_off_row(wn * 32, lane);

    float acc[4][4][4];
#pragma unroll
    for (int mi = 0; mi < 4; mi++)
#pragma unroll
        for (int ni = 0; ni < 4; ni++)
#pragma unroll
            for (int r = 0; r < 4; r++) acc[mi][ni][r] = 0.f;

    auto load_chunk = [&](int ci, int buf) {
        const int kc = ci << 5;
        __half* sA = hsm + buf * 2 * TILE_H;
        __half* sB = sA + TILE_H;
        uint32_t aBase = smem_u32(sA);
        uint32_t bBase = smem_u32(sB);
#pragma unroll
        for (int j = 0; j < 2; j++) {
            int idx = tid + j * 256;
            int row = idx >> 2, seg = idx & 3;
            cp16(aBase + (uint32_t)(row * KSTRH * 2 + seg * 16),
                 &A[(size_t)(s0 + row) * Kd + kc + seg * 8]);
            cp16(bBase + (uint32_t)(row * KSTRH * 2 + seg * 16),
                 &B[(size_t)(n0 + row) * Kd + kc + seg * 8]);
        }
        cp_commit();
    };

    load_chunk(0, 0);
    load_chunk(1, 1);

    for (int ci = 0; ci < nch; ci++) {
        if (ci + 2 < nch)      { load_chunk(ci + 2, (ci + 2) % 3); cp_wait<2>(); }
        else if (ci + 1 < nch) { cp_wait<1>(); }
        else                   { cp_wait<0>(); }
        __syncthreads();
        const uint32_t sbase = smem_u32(hsm + (ci % 3) * 2 * TILE_H);
        gemm_chunk_h2(sbase + aOff, sbase + (uint32_t)(TILE_H * 2) + bOff, acc);
        __syncthreads();
    }

#pragma unroll
    for (int ni = 0; ni < 4; ni++) {
        const int col = n0 + wn * 32 + ni * 8 + cq * 2;
        const float b0 = bias[col], b1 = bias[col + 1];
        float m0 = 0.f, m1 = 0.f, r0 = 0.f, r1 = 0.f;
        if (RESID) { m0 = mr[col]; m1 = mr[col + 1]; r0 = rr[col]; r1 = rr[col + 1]; }
        float ls0 = 0.f, ls1 = 0.f, lq0 = 0.f, lq1 = 0.f;
#pragma unroll
        for (int mi = 0; mi < 4; mi++) {
            const int row0 = s0 + wm * 64 + mi * 16 + rq;
#pragma unroll
            for (int half = 0; half < 2; half++) {
                const int row = row0 + half * 8;
                float v0 = acc[mi][ni][half * 2 + 0] + b0;
                float v1 = acc[mi][ni][half * 2 + 1] + b1;
                if (RESID) {
                    float2 rf = __half22float2(
                        *(const __half2*)&resid[(size_t)row * 128 + col]);
                    v0 += (rf.x - m0) * r0;
                    v1 += (rf.y - m1) * r1;
                }
                if (STATS) {
                    ls0 += v0; lq0 += v0 * v0;
                    ls1 += v1; lq1 += v1 * v1;
                }
                if (OUTF32) {
                    float2 o; o.x = v0; o.y = v1;
                    *(float2*)&((float*)Yv)[(size_t)row * Nout + col] = o;
                } else {
                    *(__half2*)&((__half*)Yv)[(size_t)row * Nout + col] =
                        __floats2half2_rn(v0, v1);
                }
            }
        }
        if (STATS) {
#pragma unroll
            for (int o = 4; o < 32; o <<= 1) {
                ls0 += __shfl_xor_sync(0xFFFFFFFF, ls0, o);
                ls1 += __shfl_xor_sync(0xFFFFFFFF, ls1, o);
                lq0 += __shfl_xor_sync(0xFFFFFFFF, lq0, o);
                lq1 += __shfl_xor_sync(0xFFFFFFFF, lq1, o);
            }
            if (rq == 0) {
                atomicAdd(&sstat[col - n0], ls0);
                atomicAdd(&sstat[col - n0 + 1], ls1);
                atomicAdd(&sstat[128 + col - n0], lq0);
                atomicAdd(&sstat[128 + col - n0 + 1], lq1);
            }
        }
    }
    if (STATS) {
        __syncthreads();
        if (tid < 128) {
            part[blockIdx.x * 128 + tid] = sstat[tid];
            part[S_TOT + blockIdx.x * 128 + tid] = sstat[128 + tid];
        }
    }
}

// ============================================================
// Neighborhood attention — half2 math, 1 barrier/tap, depth-2 (R13)
// ============================================================
#define SLH    136
#define SLAB_H (32 * SLH)

__global__ void __launch_bounds__(256)
attn9(const __half* __restrict__ qkv, __half* __restrict__ sam,
      const float* __restrict__ rpb)
{
    __shared__ __align__(16) __half slabs[3][SLAB_H];
    __shared__ float srpb[1000];
    __shared__ const __half* stap[19];

    const int h = blockIdx.y, w = blockIdx.x;
    const int tid = threadIdx.x;
    const int g = tid >> 5;
    const int z = tid & 31;

    const int sh = min(max(h - 1, 0), HD - 3);
    const int sw = min(max(w - 1, 0), HD - 3);
    const int sz = min(max(z - 1, 0), HD - 3);

    if (tid < 19) {
        int t = tid, nh, nw, off;
        if (t == 0)      { nh = h; nw = w; off = 0; }
        else if (t <= 9) { int j = t - 1;  nh = sh + j / 3; nw = sw + j % 3; off = 128; }
        else             { int j = t - 10; nh = sh + j / 3; nw = sw + j % 3; off = 256; }
        stap[t] = qkv + ((size_t)((nh * HD + nw) * HD)) * 384 + off;
    }
    for (int i = tid; i < 1000; i += 256) srpb[i] = rpb[i];
    __syncthreads();

    const int frow = tid >> 4;
    const int c16 = tid & 15;
    const size_t src_toff = (size_t)frow * 384 + c16 * 8;
    const uint32_t dloc = (uint32_t)(frow * SLH * 2 + c16 * 16);

    const __half* r0 = &slabs[0][0];
    const __half* r1 = &slabs[1][0];
    const __half* r2 = &slabs[2][0];
    uint32_t d0 = smem_u32(r0) + dloc;
    uint32_t d1 = smem_u32(r1) + dloc;
    uint32_t d2 = smem_u32(r2) + dloc;

    auto fill_at = [&](uint32_t d, int t) {
        const __half* src = stap[t] + src_toff;
        cp16ca(d, src);
        cp16ca(d + (uint32_t)(16 * SLH * 2), src + (size_t)16 * 384);
        cp_commit();
    };
    auto rot = [&]() {
        const __half* tr = r0; r0 = r1; r1 = r2; r2 = tr;
        uint32_t td = d0; d0 = d1; d1 = d2; d2 = td;
    };

    fill_at(d0, 0);
    fill_at(d1, 1);

    __half2 hq[8];
    cp_wait<1>();
    __syncthreads();
    fill_at(d2, 2);
    {
        uint4 qa = *(const uint4*)&r0[z * SLH + g * 16];
        uint4 qb = *(const uint4*)&r0[z * SLH + g * 16 + 8];
        hq[0] = u2h(qa.x); hq[1] = u2h(qa.y); hq[2] = u2h(qa.z); hq[3] = u2h(qa.w);
        hq[4] = u2h(qb.x); hq[5] = u2h(qb.y); hq[6] = u2h(qb.z); hq[7] = u2h(qb.w);
    }
    rot();

    float logits[27];
    const __half2 hz = __floats2half2_rn(0.f, 0.f);
    for (int j = 0; j < 9; j++) {
        cp_wait<1>();
        __syncthreads();
        fill_at(d2, j + 3);
        const __half* slab = r0;
        const int rh = sh + j / 3 - h + 2, rw = sw + j % 3 - w + 2;
        const float* rp = &srpb[g * 125 + (rh * 5 + rw) * 5 + (sz - z + 2)];
#pragma unroll
        for (int jz = 0; jz < 3; jz++) {
            const int nz = sz + jz;
            uint4 pa = *(const uint4*)&slab[nz * SLH + g * 16];
            uint4 pb = *(const uint4*)&slab[nz * SLH + g * 16 + 8];
            __half2 hd = hz;
            hd = __hfma2(hq[0], u2h(pa.x), hd);
            hd = __hfma2(hq[1], u2h(pa.y), hd);
            hd = __hfma2(hq[2], u2h(pa.z), hd);
            hd = __hfma2(hq[3], u2h(pa.w), hd);
            hd = __hfma2(hq[4], u2h(pb.x), hd);
            hd = __hfma2(hq[5], u2h(pb.y), hd);
            hd = __hfma2(hq[6], u2h(pb.z), hd);
            hd = __hfma2(hq[7], u2h(pb.w), hd);
            float2 f = __half22float2(hd);
            logits[j * 3 + jz] = (f.x + f.y) * 0.25f + rp[jz];
        }
        rot();
    }

    {
        float mx = logits[0];
#pragma unroll
        for (int j = 1; j < 27; j++) mx = fmaxf(mx, logits[j]);
        float sum = 0.f;
#pragma unroll
        for (int j = 0; j < 27; j++) { logits[j] = __expf(logits[j] - mx); sum += logits[j]; }
        const float inv = 1.f / sum;
#pragma unroll
        for (int j = 0; j < 27; j++) logits[j] *= inv;
    }

    float acc[16];
#pragma unroll
    for (int d = 0; d < 16; d++) acc[d] = 0.f;

    auto v_tap = [&](const __half* slab, int j) {
        __half2 va[8];
#pragma unroll
        for (int i = 0; i < 8; i++) va[i] = hz;
#pragma unroll
        for (int jz = 0; jz < 3; jz++) {
            const int nz = sz + jz;
            const __half2 ph = __float2half2_rn(logits[j * 3 + jz]);
            uint4 pa = *(const uint4*)&slab[nz * SLH + g * 16];
            uint4 pb = *(const uint4*)&slab[nz * SLH + g * 16 + 8];
            va[0] = __hfma2(ph, u2h(pa.x), va[0]);
            va[1] = __hfma2(ph, u2h(pa.y), va[1]);
            va[2] = __hfma2(ph, u2h(pa.z), va[2]);
            va[3] = __hfma2(ph, u2h(pa.w), va[3]);
            va[4] = __hfma2(ph, u2h(pb.x), va[4]);
            va[5] = __hfma2(ph, u2h(pb.y), va[5]);
            va[6] = __hfma2(ph, u2h(pb.z), va[6]);
            va[7] = __hfma2(ph, u2h(pb.w), va[7]);
        }
#pragma unroll
        for (int i = 0; i < 8; i++) {
            float2 f = __half22float2(va[i]);
            acc[2 * i] += f.x;
            acc[2 * i + 1] += f.y;
        }
    };

    for (int j = 0; j < 7; j++) {
        cp_wait<1>();
        __syncthreads();
        fill_at(d2, j + 12);
        v_tap(r0, j);
        rot();
    }
#pragma unroll
    for (int j = 7; j < 9; j++) {
        if (j == 7) cp_wait<1>(); else cp_wait<0>();
        __syncthreads();
        v_tap(r0, j);
        rot();
    }

    __syncthreads();
    {
        uint32_t o[8];
#pragma unroll
        for (int i = 0; i < 8; i++) {
            __half2 hh = __floats2half2_rn(acc[2 * i], acc[2 * i + 1]);
            o[i] = *reinterpret_cast<uint32_t*>(&hh);
        }
        *(uint4*)&slabs[0][z * SLH + g * 16] = make_uint4(o[0], o[1], o[2], o[3]);
        *(uint4*)&slabs[0][z * SLH + g * 16 + 8] = make_uint4(o[4], o[5], o[6], o[7]);
    }
    __syncthreads();
    {
        __half* dst = sam + ((size_t)((h * HD + w) * HD)) * 128;
        *(uint4*)&dst[(size_t)frow * 128 + c16 * 8] =
            *(const uint4*)&slabs[0][frow * SLH + c16 * 8];
        *(uint4*)&dst[(size_t)(frow + 16) * 128 + c16 * 8] =
            *(const uint4*)&slabs[0][(frow + 16) * SLH + c16 * 8];
    }
}

// ============================================================
// Fused finalize + maxpool (unchanged)
// ============================================================
#define FP_SMEM (128 * 129 * 4)

__global__ void __launch_bounds__(256)
final_pool(const float* __restrict__ t2, const float* __restrict__ x,
           const float* __restrict__ m2, const float* __restrict__ r2,
           float* __restrict__ skip, float* __restrict__ down)
{
    extern __shared__ float tt[];
    const int oh = blockIdx.y, ow = blockIdx.x;
    const int tid = threadIdx.x;
    const int wid = tid >> 5;
    const int lane = tid & 31;

    int sgbase[4];
#pragma unroll
    for (int col = 0; col < 4; col++) {
        const int hh = col >> 1, ww = col & 1;
        sgbase[col] = (((2 * oh + hh) * HD) + (2 * ow + ww)) * HD;
    }

#pragma unroll
    for (int i = 0; i < 16; i++) {
        const int idx = tid + i * 256;
        const int sl = idx >> 5;
        const int cg = idx & 31;
        const int col = sl >> 5, zz = sl & 31;
        float4 v = *(const float4*)&t2[(size_t)(sgbase[col] + zz) * 128 + cg * 4];
        float* row = &tt[sl * 129 + cg * 4];
        row[0] = v.x; row[1] = v.y; row[2] = v.z; row[3] = v.w;
    }
    __syncthreads();

    for (int cc = wid; cc < 128; cc += 8) {
        const float mv = m2[cc], rv = r2[cc];
        float vmax = -1e30f;
#pragma unroll
        for (int col = 0; col < 4; col++) {
            const int sg = sgbase[col] + lane;
            float v = (tt[(col * 32 + lane) * 129 + cc] - mv) * rv
                    + x[(size_t)cc * S_TOT + sg];
            skip[(size_t)cc * S_TOT + sg] = v;
            vmax = fmaxf(vmax, v);
        }
        float other = __shfl_down_sync(0xFFFFFFFF, vmax, 1);
        if ((lane & 1) == 0) {
            const int oz = lane >> 1;
            down[(size_t)cc * 4096 + oh * 256 + ow * 16 + oz] = fmaxf(vmax, other);
        }
    }
}

// ---------------- misc kernels ----------------
__global__ void __launch_bounds__(256)
wprep_h(const float* __restrict__ qkv_w, const float* __restrict__ proj_w,
        const float* __restrict__ w2,
        __half* __restrict__ qw, __half* __restrict__ pw,
        __half* __restrict__ w2t)
{
    int i = blockIdx.x * 256 + threadIdx.x;
    if (i < 49152) qw[i] = __float2half(qkv_w[i]);
    if (i < 16384) pw[i] = __float2half(proj_w[i]);
    int f = i >> 7, c = i & 127;
    w2t[c * 512 + f] = __float2half(w2[i]);
}

__global__ void __launch_bounds__(128)
w1fold_h(const float* __restrict__ w1, const float* __restrict__ b1,
         const float* __restrict__ m1, const float* __restrict__ r1,
         __half* __restrict__ w1f, float* __restrict__ b1f)
{
    const int f = blockIdx.x, c = threadIdx.x;
    float wv = w1[c * 512 + f] * r1[c];
    w1f[f * 128 + c] = __float2half(wv);
    __shared__ float sh[128];
    sh[c] = wv * m1[c];
    __syncthreads();
    for (int o = 64; o > 0; o >>= 1) {
        if (c < o) sh[c] += sh[c + o];
        __syncthreads();
    }
    if (c == 0) b1f[f] = b1[f] - sh[0];
}

__global__ void __launch_bounds__(128)
stats_final(const float* __restrict__ part, float* __restrict__ mean,
            float* __restrict__ rstd)
{
    const int c = threadIdx.x;
    float s = 0.f, s2 = 0.f;
    for (int b = 0; b < 256; b++) {
        s  += part[b * 128 + c];
        s2 += part[S_TOT + b * 128 + c];
    }
    const float m = s * (1.f / S_TOT);
    mean[c] = m;
    rstd[c] = rsqrtf(s2 * (1.f / S_TOT) - m * m + 1e-5f);
}

// ============================================================
extern "C" void kernel_launch(void* const* d_in, const int* in_sizes, int n_in,
                              void* d_out, int out_size)
{
    const float* x      = (const float*)d_in[0];
    const float* qkv_w  = (const float*)d_in[1];
    const float* qkv_b  = (const float*)d_in[2];
    const float* proj_w = (const float*)d_in[3];
    const float* proj_b = (const float*)d_in[4];
    const float* rpb    = (const float*)d_in[5];
    const float* w1     = (const float*)d_in[6];
    const float* b1     = (const float*)d_in[7];
    const float* w2     = (const float*)d_in[8];
    const float* b2     = (const float*)d_in[9];

    __half *qkv, *sam, *y1, *hid, *qw, *pw, *w1f, *w2t;
    float *t2, *b1f, *part, *st;
    cudaGetSymbolAddress((void**)&qkv, g_qkv);
    cudaGetSymbolAddress((void**)&sam, g_sam);
    cudaGetSymbolAddress((void**)&y1,  g_y1);
    cudaGetSymbolAddress((void**)&hid, g_hid);
    cudaGetSymbolAddress((void**)&t2,  g_t2);
    cudaGetSymbolAddress((void**)&qw,  g_qw);
    cudaGetSymbolAddress((void**)&pw,  g_pw);
    cudaGetSymbolAddress((void**)&w1f, g_w1f);
    cudaGetSymbolAddress((void**)&w2t, g_w2t);
    cudaGetSymbolAddress((void**)&b1f, g_b1f);
    cudaGetSymbolAddress((void**)&part,g_part);
    cudaGetSymbolAddress((void**)&st,  g_stats);
    float *m1 = st, *r1 = st + 128, *m2 = st + 256, *r2 = st + 384;

    const int SMEMH = 6 * TILE_H * sizeof(__half);   // 61440 B
    cudaFuncSetAttribute(gemm_anc_h<false,3,true>,
                         cudaFuncAttributeMaxDynamicSharedMemorySize, SMEMH);
    cudaFuncSetAttribute(gemm_anc_h<true,4,false>,
                         cudaFuncAttributeMaxDynamicSharedMemorySize, SMEMH);
    cudaFuncSetAttribute(gemm_h<false,false,true>,
                         cudaFuncAttributeMaxDynamicSharedMemorySize, SMEMH);
    cudaFuncSetAttribute(gemm_h<true,true,true>,
                         cudaFuncAttributeMaxDynamicSharedMemorySize, SMEMH);
    cudaFuncSetAttribute(final_pool,
                         cudaFuncAttributeMaxDynamicSharedMemorySize, FP_SMEM);

    // prep
    wprep_h<<<256, 256>>>(qkv_w, proj_w, w2, qw, pw, w2t);

    // 1) QKV (transpose fused)
    gemm_anc_h<false,3,true><<<256, 256, SMEMH>>>(
        nullptr, x, qw, qkv, qkv_b, 384);

    // 2) attention
    attn9<<<dim3(HD, HD), 256>>>(qkv, sam, rpb);

    // 3) proj -> y1 fp16, fused stats
    gemm_h<false,false,true><<<dim3(256, 1), 256, SMEMH>>>(
        sam, pw, (void*)y1, proj_b, 128, 128, nullptr, nullptr, nullptr, part);

    // 4) stats + fold into fc1
    stats_final<<<1, 128>>>(part, m1, r1);
    w1fold_h<<<512, 128>>>(w1, b1, m1, r1, w1f, b1f);

    // 5) fc1 + relu -> hid fp16
    gemm_anc_h<true,4,false><<<256, 256, SMEMH>>>(
        y1, nullptr, w1f, hid, b1f, 512);

    // 6) fc2 + normalized residual -> t2 fp32, fused stats
    gemm_h<true,true,true><<<dim3(256, 1), 256, SMEMH>>>(
        hid, w2t, (void*)t2, b2, 512, 128, y1, m1, r1, part);

    // 7) stats
    stats_final<<<1, 128>>>(part, m2, r2);

    // 8+9) fused finalize + maxpool
    float* out  = (float*)d_out;
    float* down = out;
    float* skip = out + 524288;
    final_pool<<<dim3(16, 16), 256, FP_SMEM>>>(t2, x, m2, r2, skip, down);
}

// round 17
// speedup vs baseline: 1.0135x; 1.0135x over previous
#include <cuda_runtime.h>
#include <cuda_fp16.h>
#include <stdint.h>
#include <math.h>

#define S_TOT 32768
#define HD 32

// ---------------- scratch ----------------
__device__ __half g_qkv [S_TOT * 384];
__device__ __half g_sam [S_TOT * 128];
__device__ __half g_y1  [S_TOT * 128];
__device__ __half g_hid [S_TOT * 512];
__device__ float  g_t2  [S_TOT * 128];
__device__ __half g_qw  [384 * 128];
__device__ __half g_pw  [128 * 128];
__device__ __half g_w1f [512 * 128];
__device__ __half g_w2t [128 * 512];
__device__ float  g_b1f [512];
__device__ float  g_part[2 * S_TOT];
__device__ float  g_stats[512];         // m1,r1,m2,r2

// ---------------- helpers ----------------
__device__ __forceinline__ uint32_t smem_u32(const void* p) {
    uint32_t a;
    asm("{ .reg .u64 t; cvta.to.shared.u64 t, %1; cvt.u32.u64 %0, t; }"
        : "=r"(a) : "l"(p));
    return a;
}
__device__ __forceinline__ void cp16(uint32_t s, const void* g) {
    asm volatile("cp.async.cg.shared.global [%0], [%1], 16;" :: "r"(s), "l"(g));
}
__device__ __forceinline__ void cp16ca(uint32_t s, const void* g) {
    asm volatile("cp.async.ca.shared.global [%0], [%1], 16;" :: "r"(s), "l"(g));
}
__device__ __forceinline__ void cp_commit() {
    asm volatile("cp.async.commit_group;" ::: "memory");
}
template<int N>
__device__ __forceinline__ void cp_wait() {
    asm volatile("cp.async.wait_group %0;" :: "n"(N) : "memory");
}
__device__ __forceinline__ void ldsm4(uint32_t* r, uint32_t addr) {
    asm volatile("ldmatrix.sync.aligned.m8n8.x4.shared.b16 {%0,%1,%2,%3}, [%4];"
        : "=r"(r[0]), "=r"(r[1]), "=r"(r[2]), "=r"(r[3]) : "r"(addr));
}
__device__ __forceinline__ __half2 u2h(uint32_t u) {
    return *reinterpret_cast<__half2*>(&u);
}

// fp16 GEMM tiling: K-chunk 32 halfs, row stride 40 halfs
#define KSTRH 40
#define TILE_H (128 * KSTRH)

#define MMA_F16(acc, a, b) \
    asm volatile( \
        "mma.sync.aligned.m16n8k16.row.col.f32.f16.f16.f32 " \
        "{%0,%1,%2,%3}, {%4,%5,%6,%7}, {%8,%9}, {%0,%1,%2,%3};" \
        : "+f"((acc)[0]), "+f"((acc)[1]), "+f"((acc)[2]), "+f"((acc)[3]) \
        : "r"((a)[0]), "r"((a)[1]), "r"((a)[2]), "r"((a)[3]), \
          "r"((b)[0]), "r"((b)[1]))

__device__ __forceinline__ uint32_t frag_off_row(int rowbase, int lane) {
    return (uint32_t)((rowbase + (lane & 15)) * (KSTRH * 2)
                      + ((lane >> 4) & 1) * 16);
}

// ---- warp tile 64x64 (for 128-thread A-resident kernels) ----
__device__ __forceinline__ void gemm_chunk_h(
    uint32_t aBase, uint32_t bBase, float acc[4][8][4])
{
#pragma unroll
    for (int ks = 0; ks < 2; ks++) {
        uint32_t a[4][4], b[8][2];
#pragma unroll
        for (int mi = 0; mi < 4; mi++)
            ldsm4(a[mi], aBase + (uint32_t)(mi * 16 * KSTRH * 2 + ks * 32));
#pragma unroll
        for (int n2 = 0; n2 < 4; n2++) {
            uint32_t r[4];
            ldsm4(r, bBase + (uint32_t)(n2 * 16 * KSTRH * 2 + ks * 32));
            b[2 * n2][0] = r[0]; b[2 * n2][1] = r[2];
            b[2 * n2 + 1][0] = r[1]; b[2 * n2 + 1][1] = r[3];
        }
#pragma unroll
        for (int mi = 0; mi < 4; mi++)
#pragma unroll
            for (int ni = 0; ni < 8; ni++)
                MMA_F16(acc[mi][ni], a[mi], b[ni]);
    }
}

// ---- warp tile 64x32 (for 256-thread streaming kernels) ----
__device__ __forceinline__ void gemm_chunk_h2(
    uint32_t aBase, uint32_t bBase, float acc[4][4][4])
{
#pragma unroll
    for (int ks = 0; ks < 2; ks++) {
        uint32_t a[4][4], b[4][2];
#pragma unroll
        for (int mi = 0; mi < 4; mi++)
            ldsm4(a[mi], aBase + (uint32_t)(mi * 16 * KSTRH * 2 + ks * 32));
#pragma unroll
        for (int n2 = 0; n2 < 2; n2++) {
            uint32_t r[4];
            ldsm4(r, bBase + (uint32_t)(n2 * 16 * KSTRH * 2 + ks * 32));
            b[2 * n2][0] = r[0]; b[2 * n2][1] = r[2];
            b[2 * n2 + 1][0] = r[1]; b[2 * n2 + 1][1] = r[3];
        }
#pragma unroll
        for (int mi = 0; mi < 4; mi++)
#pragma unroll
            for (int ni = 0; ni < 4; ni++)
                MMA_F16(acc[mi][ni], a[mi], b[ni]);
    }
}

// ============================================================
// A-resident multi-N fp16 GEMM (QKV, fc1) — R15 128-thread version.
// TRANSX: A read from fp32 x [C, S_TOT], transposed+converted on load.
// smem: 4 A tiles + 2 B tiles = 61440 B.
// ============================================================
template<bool RELU, int NC, bool TRANSX>
__global__ void __launch_bounds__(128)
gemm_anc_h(const __half* __restrict__ A, const float* __restrict__ Ax,
           const __half* __restrict__ B,
           __half* __restrict__ Y, const float* __restrict__ bias, int Nout)
{
    extern __shared__ __half hsm[];

    const int tid = threadIdx.x;
    const int wid = tid >> 5;
    const int lane = tid & 31;
    const int wm = wid & 1;
    const int wn = wid >> 1;
    const int rq = lane >> 2;
    const int cq = lane & 3;
    const int s0 = blockIdx.x * 128;

    const uint32_t aOff = frag_off_row(wm * 64, lane);
    const uint32_t bOff = frag_off_row(wn * 64, lane);

    if (TRANSX) {
        // warp wid covers channels wid*32 + i; lanes cover S (coalesced)
#pragma unroll 4
        for (int i = 0; i < 32; i++) {
            const int c = wid * 32 + i;
            float4 v = *(const float4*)&Ax[(size_t)c * S_TOT + s0 + lane * 4];
            const int kc = c >> 5, cc = c & 31;
            __half* base = hsm + kc * TILE_H + cc;
            base[(lane * 4 + 0) * KSTRH] = __float2half(v.x);
            base[(lane * 4 + 1) * KSTRH] = __float2half(v.y);
            base[(lane * 4 + 2) * KSTRH] = __float2half(v.z);
            base[(lane * 4 + 3) * KSTRH] = __float2half(v.w);
        }
    } else {
#pragma unroll
        for (int kc = 0; kc < 4; kc++) {
            uint32_t aBase = smem_u32(hsm + kc * TILE_H);
#pragma unroll
            for (int j = 0; j < 4; j++) {
                int idx = tid + j * 128;
                int row = idx >> 2, seg = idx & 3;
                cp16(aBase + (uint32_t)(row * KSTRH * 2 + seg * 16),
                     &A[(size_t)(s0 + row) * 128 + kc * 32 + seg * 8]);
            }
        }
        cp_commit();
    }

    auto load_B = [&](int idx, int buf) {
        const int nc = idx >> 2, kc = idx & 3;
        uint32_t bBase = smem_u32(hsm + (4 + buf) * TILE_H);
#pragma unroll
        for (int j = 0; j < 4; j++) {
            int l = tid + j * 128;
            int row = l >> 2, seg = l & 3;
            cp16(bBase + (uint32_t)(row * KSTRH * 2 + seg * 16),
                 &B[(size_t)(nc * 128 + row) * 128 + kc * 32 + seg * 8]);
        }
        cp_commit();
    };

    load_B(0, 0);

    for (int nc = 0; nc < NC; nc++) {
        float acc[4][8][4];
#pragma unroll
        for (int mi = 0; mi < 4; mi++)
#pragma unroll
            for (int ni = 0; ni < 8; ni++)
#pragma unroll
                for (int r = 0; r < 4; r++) acc[mi][ni][r] = 0.f;

        for (int kc = 0; kc < 4; kc++) {
            const int idx = nc * 4 + kc;
            if (idx + 1 < NC * 4) { load_B(idx + 1, (idx + 1) & 1); cp_wait<1>(); }
            else                  { cp_wait<0>(); }
            __syncthreads();
            gemm_chunk_h(smem_u32(hsm + kc * TILE_H) + aOff,
                         smem_u32(hsm + (4 + (idx & 1)) * TILE_H) + bOff, acc);
            __syncthreads();
        }

        const int n0 = nc * 128;
#pragma unroll
        for (int ni = 0; ni < 8; ni++) {
            const int col = n0 + wn * 64 + ni * 8 + cq * 2;
            const float b0 = bias[col], b1 = bias[col + 1];
#pragma unroll
            for (int mi = 0; mi < 4; mi++) {
                const int row0 = s0 + wm * 64 + mi * 16 + rq;
#pragma unroll
                for (int half = 0; half < 2; half++) {
                    const int row = row0 + half * 8;
                    float v0 = acc[mi][ni][half * 2 + 0] + b0;
                    float v1 = acc[mi][ni][half * 2 + 1] + b1;
                    if (RELU) { v0 = fmaxf(v0, 0.f); v1 = fmaxf(v1, 0.f); }
                    *(__half2*)&Y[(size_t)row * Nout + col] =
                        __floats2half2_rn(v0, v1);
                }
            }
        }
    }
}

// ============================================================
// Streaming fp16 GEMM (proj, fc2) — R16 256-thread version, fused stats.
// ============================================================
template<bool RESID, bool OUTF32, bool STATS>
__global__ void __launch_bounds__(256)
gemm_h(const __half* __restrict__ A, const __half* __restrict__ B,
       void* __restrict__ Yv, const float* __restrict__ bias,
       int Kd, int Nout, const __half* __restrict__ resid,
       const float* __restrict__ mr, const float* __restrict__ rr,
       float* __restrict__ part)
{
    extern __shared__ __half hsm[];
    __shared__ float sstat[256];

    const int tid = threadIdx.x;
    const int wid = tid >> 5;
    const int lane = tid & 31;
    const int wm = wid & 1;
    const int wn = wid >> 1;
    const int rq = lane >> 2;
    const int cq = lane & 3;
    const int s0 = blockIdx.x * 128;
    const int n0 = blockIdx.y * 128;

    if (STATS) { sstat[tid] = 0.f; }

    const int nch = Kd >> 5;
    const uint32_t aOff = frag_off_row(wm * 64, lane);
    const uint32_t bOff = frag_off_row(wn * 32, lane);

    float acc[4][4][4];
#pragma unroll
    for (int mi = 0; mi < 4; mi++)
#pragma unroll
        for (int ni = 0; ni < 4; ni++)
#pragma unroll
            for (int r = 0; r < 4; r++) acc[mi][ni][r] = 0.f;

    auto load_chunk = [&](int ci, int buf) {
        const int kc = ci << 5;
        __half* sA = hsm + buf * 2 * TILE_H;
        __half* sB = sA + TILE_H;
        uint32_t aBase = smem_u32(sA);
        uint32_t bBase = smem_u32(sB);
#pragma unroll
        for (int j = 0; j < 2; j++) {
            int idx = tid + j * 256;
            int row = idx >> 2, seg = idx & 3;
            cp16(aBase + (uint32_t)(row * KSTRH * 2 + seg * 16),
                 &A[(size_t)(s0 + row) * Kd + kc + seg * 8]);
            cp16(bBase + (uint32_t)(row * KSTRH * 2 + seg * 16),
                 &B[(size_t)(n0 + row) * Kd + kc + seg * 8]);
        }
        cp_commit();
    };

    load_chunk(0, 0);
    load_chunk(1, 1);

    for (int ci = 0; ci < nch; ci++) {
        if (ci + 2 < nch)      { load_chunk(ci + 2, (ci + 2) % 3); cp_wait<2>(); }
        else if (ci + 1 < nch) { cp_wait<1>(); }
        else                   { cp_wait<0>(); }
        __syncthreads();
        const uint32_t sbase = smem_u32(hsm + (ci % 3) * 2 * TILE_H);
        gemm_chunk_h2(sbase + aOff, sbase + (uint32_t)(TILE_H * 2) + bOff, acc);
        __syncthreads();
    }

#pragma unroll
    for (int ni = 0; ni < 4; ni++) {
        const int col = n0 + wn * 32 + ni * 8 + cq * 2;
        const float b0 = bias[col], b1 = bias[col + 1];
        float m0 = 0.f, m1 = 0.f, r0 = 0.f, r1 = 0.f;
        if (RESID) { m0 = mr[col]; m1 = mr[col + 1]; r0 = rr[col]; r1 = rr[col + 1]; }
        float ls0 = 0.f, ls1 = 0.f, lq0 = 0.f, lq1 = 0.f;
#pragma unroll
        for (int mi = 0; mi < 4; mi++) {
            const int row0 = s0 + wm * 64 + mi * 16 + rq;
#pragma unroll
            for (int half = 0; half < 2; half++) {
                const int row = row0 + half * 8;
                float v0 = acc[mi][ni][half * 2 + 0] + b0;
                float v1 = acc[mi][ni][half * 2 + 1] + b1;
                if (RESID) {
                    float2 rf = __half22float2(
                        *(const __half2*)&resid[(size_t)row * 128 + col]);
                    v0 += (rf.x - m0) * r0;
                    v1 += (rf.y - m1) * r1;
                }
                if (STATS) {
                    ls0 += v0; lq0 += v0 * v0;
                    ls1 += v1; lq1 += v1 * v1;
                }
                if (OUTF32) {
                    float2 o; o.x = v0; o.y = v1;
                    *(float2*)&((float*)Yv)[(size_t)row * Nout + col] = o;
                } else {
                    *(__half2*)&((__half*)Yv)[(size_t)row * Nout + col] =
                        __floats2half2_rn(v0, v1);
                }
            }
        }
        if (STATS) {
#pragma unroll
            for (int o = 4; o < 32; o <<= 1) {
                ls0 += __shfl_xor_sync(0xFFFFFFFF, ls0, o);
                ls1 += __shfl_xor_sync(0xFFFFFFFF, ls1, o);
                lq0 += __shfl_xor_sync(0xFFFFFFFF, lq0, o);
                lq1 += __shfl_xor_sync(0xFFFFFFFF, lq1, o);
            }
            if (rq == 0) {
                atomicAdd(&sstat[col - n0], ls0);
                atomicAdd(&sstat[col - n0 + 1], ls1);
                atomicAdd(&sstat[128 + col - n0], lq0);
                atomicAdd(&sstat[128 + col - n0 + 1], lq1);
            }
        }
    }
    if (STATS) {
        __syncthreads();
        if (tid < 128) {
            part[blockIdx.x * 128 + tid] = sstat[tid];
            part[S_TOT + blockIdx.x * 128 + tid] = sstat[128 + tid];
        }
    }
}

// ============================================================
// Neighborhood attention — half2 math, 1 barrier/tap, depth-2 (R13)
// ============================================================
#define SLH    136
#define SLAB_H (32 * SLH)

__global__ void __launch_bounds__(256)
attn9(const __half* __restrict__ qkv, __half* __restrict__ sam,
      const float* __restrict__ rpb)
{
    __shared__ __align__(16) __half slabs[3][SLAB_H];
    __shared__ float srpb[1000];
    __shared__ const __half* stap[19];

    const int h = blockIdx.y, w = blockIdx.x;
    const int tid = threadIdx.x;
    const int g = tid >> 5;
    const int z = tid & 31;

    const int sh = min(max(h - 1, 0), HD - 3);
    const int sw = min(max(w - 1, 0), HD - 3);
    const int sz = min(max(z - 1, 0), HD - 3);

    if (tid < 19) {
        int t = tid, nh, nw, off;
        if (t == 0)      { nh = h; nw = w; off = 0; }
        else if (t <= 9) { int j = t - 1;  nh = sh + j / 3; nw = sw + j % 3; off = 128; }
        else             { int j = t - 10; nh = sh + j / 3; nw = sw + j % 3; off = 256; }
        stap[t] = qkv + ((size_t)((nh * HD + nw) * HD)) * 384 + off;
    }
    for (int i = tid; i < 1000; i += 256) srpb[i] = rpb[i];
    __syncthreads();

    const int frow = tid >> 4;
    const int c16 = tid & 15;
    const size_t src_toff = (size_t)frow * 384 + c16 * 8;
    const uint32_t dloc = (uint32_t)(frow * SLH * 2 + c16 * 16);

    const __half* r0 = &slabs[0][0];
    const __half* r1 = &slabs[1][0];
    const __half* r2 = &slabs[2][0];
    uint32_t d0 = smem_u32(r0) + dloc;
    uint32_t d1 = smem_u32(r1) + dloc;
    uint32_t d2 = smem_u32(r2) + dloc;

    auto fill_at = [&](uint32_t d, int t) {
        const __half* src = stap[t] + src_toff;
        cp16ca(d, src);
        cp16ca(d + (uint32_t)(16 * SLH * 2), src + (size_t)16 * 384);
        cp_commit();
    };
    auto rot = [&]() {
        const __half* tr = r0; r0 = r1; r1 = r2; r2 = tr;
        uint32_t td = d0; d0 = d1; d1 = d2; d2 = td;
    };

    fill_at(d0, 0);
    fill_at(d1, 1);

    __half2 hq[8];
    cp_wait<1>();
    __syncthreads();
    fill_at(d2, 2);
    {
        uint4 qa = *(const uint4*)&r0[z * SLH + g * 16];
        uint4 qb = *(const uint4*)&r0[z * SLH + g * 16 + 8];
        hq[0] = u2h(qa.x); hq[1] = u2h(qa.y); hq[2] = u2h(qa.z); hq[3] = u2h(qa.w);
        hq[4] = u2h(qb.x); hq[5] = u2h(qb.y); hq[6] = u2h(qb.z); hq[7] = u2h(qb.w);
    }
    rot();

    float logits[27];
    const __half2 hz = __floats2half2_rn(0.f, 0.f);
    for (int j = 0; j < 9; j++) {
        cp_wait<1>();
        __syncthreads();
        fill_at(d2, j + 3);
        const __half* slab = r0;
        const int rh = sh + j / 3 - h + 2, rw = sw + j % 3 - w + 2;
        const float* rp = &srpb[g * 125 + (rh * 5 + rw) * 5 + (sz - z + 2)];
#pragma unroll
        for (int jz = 0; jz < 3; jz++) {
            const int nz = sz + jz;
            uint4 pa = *(const uint4*)&slab[nz * SLH + g * 16];
            uint4 pb = *(const uint4*)&slab[nz * SLH + g * 16 + 8];
            __half2 hd = hz;
            hd = __hfma2(hq[0], u2h(pa.x), hd);
            hd = __hfma2(hq[1], u2h(pa.y), hd);
            hd = __hfma2(hq[2], u2h(pa.z), hd);
            hd = __hfma2(hq[3], u2h(pa.w), hd);
            hd = __hfma2(hq[4], u2h(pb.x), hd);
            hd = __hfma2(hq[5], u2h(pb.y), hd);
            hd = __hfma2(hq[6], u2h(pb.z), hd);
            hd = __hfma2(hq[7], u2h(pb.w), hd);
            float2 f = __half22float2(hd);
            logits[j * 3 + jz] = (f.x + f.y) * 0.25f + rp[jz];
        }
        rot();
    }

    {
        float mx = logits[0];
#pragma unroll
        for (int j = 1; j < 27; j++) mx = fmaxf(mx, logits[j]);
        float sum = 0.f;
#pragma unroll
        for (int j = 0; j < 27; j++) { logits[j] = __expf(logits[j] - mx); sum += logits[j]; }
        const float inv = 1.f / sum;
#pragma unroll
        for (int j = 0; j < 27; j++) logits[j] *= inv;
    }

    float acc[16];
#pragma unroll
    for (int d = 0; d < 16; d++) acc[d] = 0.f;

    auto v_tap = [&](const __half* slab, int j) {
        __half2 va[8];
#pragma unroll
        for (int i = 0; i < 8; i++) va[i] = hz;
#pragma unroll
        for (int jz = 0; jz < 3; jz++) {
            const int nz = sz + jz;
            const __half2 ph = __float2half2_rn(logits[j * 3 + jz]);
            uint4 pa = *(const uint4*)&slab[nz * SLH + g * 16];
            uint4 pb = *(const uint4*)&slab[nz * SLH + g * 16 + 8];
            va[0] = __hfma2(ph, u2h(pa.x), va[0]);
            va[1] = __hfma2(ph, u2h(pa.y), va[1]);
            va[2] = __hfma2(ph, u2h(pa.z), va[2]);
            va[3] = __hfma2(ph, u2h(pa.w), va[3]);
            va[4] = __hfma2(ph, u2h(pb.x), va[4]);
            va[5] = __hfma2(ph, u2h(pb.y), va[5]);
            va[6] = __hfma2(ph, u2h(pb.z), va[6]);
            va[7] = __hfma2(ph, u2h(pb.w), va[7]);
        }
#pragma unroll
        for (int i = 0; i < 8; i++) {
            float2 f = __half22float2(va[i]);
            acc[2 * i] += f.x;
            acc[2 * i + 1] += f.y;
        }
    };

    for (int j = 0; j < 7; j++) {
        cp_wait<1>();
        __syncthreads();
        fill_at(d2, j + 12);
        v_tap(r0, j);
        rot();
    }
#pragma unroll
    for (int j = 7; j < 9; j++) {
        if (j == 7) cp_wait<1>(); else cp_wait<0>();
        __syncthreads();
        v_tap(r0, j);
        rot();
    }

    __syncthreads();
    {
        uint32_t o[8];
#pragma unroll
        for (int i = 0; i < 8; i++) {
            __half2 hh = __floats2half2_rn(acc[2 * i], acc[2 * i + 1]);
            o[i] = *reinterpret_cast<uint32_t*>(&hh);
        }
        *(uint4*)&slabs[0][z * SLH + g * 16] = make_uint4(o[0], o[1], o[2], o[3]);
        *(uint4*)&slabs[0][z * SLH + g * 16 + 8] = make_uint4(o[4], o[5], o[6], o[7]);
    }
    __syncthreads();
    {
        __half* dst = sam + ((size_t)((h * HD + w) * HD)) * 128;
        *(uint4*)&dst[(size_t)frow * 128 + c16 * 8] =
            *(const uint4*)&slabs[0][frow * SLH + c16 * 8];
        *(uint4*)&dst[(size_t)(frow + 16) * 128 + c16 * 8] =
            *(const uint4*)&slabs[0][(frow + 16) * SLH + c16 * 8];
    }
}

// ============================================================
// Fused finalize + maxpool (unchanged)
// ============================================================
#define FP_SMEM (128 * 129 * 4)

__global__ void __launch_bounds__(256)
final_pool(const float* __restrict__ t2, const float* __restrict__ x,
           const float* __restrict__ m2, const float* __restrict__ r2,
           float* __restrict__ skip, float* __restrict__ down)
{
    extern __shared__ float tt[];
    const int oh = blockIdx.y, ow = blockIdx.x;
    const int tid = threadIdx.x;
    const int wid = tid >> 5;
    const int lane = tid & 31;

    int sgbase[4];
#pragma unroll
    for (int col = 0; col < 4; col++) {
        const int hh = col >> 1, ww = col & 1;
        sgbase[col] = (((2 * oh + hh) * HD) + (2 * ow + ww)) * HD;
    }

#pragma unroll
    for (int i = 0; i < 16; i++) {
        const int idx = tid + i * 256;
        const int sl = idx >> 5;
        const int cg = idx & 31;
        const int col = sl >> 5, zz = sl & 31;
        float4 v = *(const float4*)&t2[(size_t)(sgbase[col] + zz) * 128 + cg * 4];
        float* row = &tt[sl * 129 + cg * 4];
        row[0] = v.x; row[1] = v.y; row[2] = v.z; row[3] = v.w;
    }
    __syncthreads();

    for (int cc = wid; cc < 128; cc += 8) {
        const float mv = m2[cc], rv = r2[cc];
        float vmax = -1e30f;
#pragma unroll
        for (int col = 0; col < 4; col++) {
            const int sg = sgbase[col] + lane;
            float v = (tt[(col * 32 + lane) * 129 + cc] - mv) * rv
                    + x[(size_t)cc * S_TOT + sg];
            skip[(size_t)cc * S_TOT + sg] = v;
            vmax = fmaxf(vmax, v);
        }
        float other = __shfl_down_sync(0xFFFFFFFF, vmax, 1);
        if ((lane & 1) == 0) {
            const int oz = lane >> 1;
            down[(size_t)cc * 4096 + oh * 256 + ow * 16 + oz] = fmaxf(vmax, other);
        }
    }
}

// ---------------- misc kernels ----------------
__global__ void __launch_bounds__(256)
wprep_h(const float* __restrict__ qkv_w, const float* __restrict__ proj_w,
        const float* __restrict__ w2,
        __half* __restrict__ qw, __half* __restrict__ pw,
        __half* __restrict__ w2t)
{
    int i = blockIdx.x * 256 + threadIdx.x;
    if (i < 49152) qw[i] = __float2half(qkv_w[i]);
    if (i < 16384) pw[i] = __float2half(proj_w[i]);
    int f = i >> 7, c = i & 127;
    w2t[c * 512 + f] = __float2half(w2[i]);
}

__global__ void __launch_bounds__(128)
w1fold_h(const float* __restrict__ w1, const float* __restrict__ b1,
         const float* __restrict__ m1, const float* __restrict__ r1,
         __half* __restrict__ w1f, float* __restrict__ b1f)
{
    const int f = blockIdx.x, c = threadIdx.x;
    float wv = w1[c * 512 + f] * r1[c];
    w1f[f * 128 + c] = __float2half(wv);
    __shared__ float sh[128];
    sh[c] = wv * m1[c];
    __syncthreads();
    for (int o = 64; o > 0; o >>= 1) {
        if (c < o) sh[c] += sh[c + o];
        __syncthreads();
    }
    if (c == 0) b1f[f] = b1[f] - sh[0];
}

__global__ void __launch_bounds__(128)
stats_final(const float* __restrict__ part, float* __restrict__ mean,
            float* __restrict__ rstd)
{
    const int c = threadIdx.x;
    float s = 0.f, s2 = 0.f;
    for (int b = 0; b < 256; b++) {
        s  += part[b * 128 + c];
        s2 += part[S_TOT + b * 128 + c];
    }
    const float m = s * (1.f / S_TOT);
    mean[c] = m;
    rstd[c] = rsqrtf(s2 * (1.f / S_TOT) - m * m + 1e-5f);
}

// ============================================================
extern "C" void kernel_launch(void* const* d_in, const int* in_sizes, int n_in,
                              void* d_out, int out_size)
{
    const float* x      = (const float*)d_in[0];
    const float* qkv_w  = (const float*)d_in[1];
    const float* qkv_b  = (const float*)d_in[2];
    const float* proj_w = (const float*)d_in[3];
    const float* proj_b = (const float*)d_in[4];
    const float* rpb    = (const float*)d_in[5];
    const float* w1     = (const float*)d_in[6];
    const float* b1     = (const float*)d_in[7];
    const float* w2     = (const float*)d_in[8];
    const float* b2     = (const float*)d_in[9];

    __half *qkv, *sam, *y1, *hid, *qw, *pw, *w1f, *w2t;
    float *t2, *b1f, *part, *st;
    cudaGetSymbolAddress((void**)&qkv, g_qkv);
    cudaGetSymbolAddress((void**)&sam, g_sam);
    cudaGetSymbolAddress((void**)&y1,  g_y1);
    cudaGetSymbolAddress((void**)&hid, g_hid);
    cudaGetSymbolAddress((void**)&t2,  g_t2);
    cudaGetSymbolAddress((void**)&qw,  g_qw);
    cudaGetSymbolAddress((void**)&pw,  g_pw);
    cudaGetSymbolAddress((void**)&w1f, g_w1f);
    cudaGetSymbolAddress((void**)&w2t, g_w2t);
    cudaGetSymbolAddress((void**)&b1f, g_b1f);
    cudaGetSymbolAddress((void**)&part,g_part);
    cudaGetSymbolAddress((void**)&st,  g_stats);
    float *m1 = st, *r1 = st + 128, *m2 = st + 256, *r2 = st + 384;

    const int SMEMH = 6 * TILE_H * sizeof(__half);   // 61440 B
    cudaFuncSetAttribute(gemm_anc_h<false,3,true>,
                         cudaFuncAttributeMaxDynamicSharedMemorySize, SMEMH);
    cudaFuncSetAttribute(gemm_anc_h<true,4,false>,
                         cudaFuncAttributeMaxDynamicSharedMemorySize, SMEMH);
    cudaFuncSetAttribute(gemm_h<false,false,true>,
                         cudaFuncAttributeMaxDynamicSharedMemorySize, SMEMH);
    cudaFuncSetAttribute(gemm_h<true,true,true>,
                         cudaFuncAttributeMaxDynamicSharedMemorySize, SMEMH);
    cudaFuncSetAttribute(final_pool,
                         cudaFuncAttributeMaxDynamicSharedMemorySize, FP_SMEM);

    // prep
    wprep_h<<<256, 256>>>(qkv_w, proj_w, w2, qw, pw, w2t);

    // 1) QKV (transpose fused; 128-thread A-resident)
    gemm_anc_h<false,3,true><<<256, 128, SMEMH>>>(
        nullptr, x, qw, qkv, qkv_b, 384);

    // 2) attention
    attn9<<<dim3(HD, HD), 256>>>(qkv, sam, rpb);

    // 3) proj -> y1 fp16, fused stats (256-thread streaming)
    gemm_h<false,false,true><<<dim3(256, 1), 256, SMEMH>>>(
        sam, pw, (void*)y1, proj_b, 128, 128, nullptr, nullptr, nullptr, part);

    // 4) stats + fold into fc1
    stats_final<<<1, 128>>>(part, m1, r1);
    w1fold_h<<<512, 128>>>(w1, b1, m1, r1, w1f, b1f);

    // 5) fc1 + relu -> hid fp16 (128-thread A-resident)
    gemm_anc_h<true,4,false><<<256, 128, SMEMH>>>(
        y1, nullptr, w1f, hid, b1f, 512);

    // 6) fc2 + normalized residual -> t2 fp32, fused stats (256-thread)
    gemm_h<true,true,true><<<dim3(256, 1), 256, SMEMH>>>(
        hid, w2t, (void*)t2, b2, 512, 128, y1, m1, r1, part);

    // 7) stats
    stats_final<<<1, 128>>>(part, m2, r2);

    // 8+9) fused finalize + maxpool
    float* out  = (float*)d_out;
    float* down = out;
    float* skip = out + 524288;
    final_pool<<<dim3(16, 16), 256, FP_SMEM>>>(t2, x, m2, r2, skip, down);
}